// round 6
// baseline (speedup 1.0000x reference)
#include <cuda_runtime.h>

#define N_NODES 100000
#define IN_C    128
#define HC      256
#define NHEAD   4
#define CDIM    64
#define NE      1600000
#define NEG     0.2f
#define BNEPS   1e-5f

// ---- device scratch (allocation-free: __device__ globals) ----
__device__ float g_h[N_NODES * HC];          // projected features  [N,256]
__device__ float g_asrc[N_NODES * NHEAD];    // per-node src logits [N,4]
__device__ float g_adst[N_NODES * NHEAD];    // per-node dst logits [N,4]
__device__ int   g_cnt[N_NODES];             // in-degree histogram
__device__ int   g_rowptr[N_NODES + 1];      // CSR row pointers (by dst)
__device__ int   g_fill[N_NODES];            // fill cursors
__device__ int   g_csr[NE];                  // src ids grouped by dst
__device__ int   g_part[128];                // scan partials
__device__ int   g_part2[128];
__device__ float g_stat[2 * HC];             // per-channel sum / sumsq
__device__ float g_scale[HC];
__device__ float g_shift[HC];
__device__ int   g_i64;                      // 1 if edge_index is int64

// ---------------------------------------------------------------------------
// Probe edge_index dtype: if the buffer is int64 (values < 2^31), every odd
// int32 word is 0. For genuine int32 random ids in [0,100000) the chance that
// 1024 sampled words are all zero is ~0.
__global__ void probe_kernel(const int* __restrict__ ei32) {
    int v = 0;
    for (int k = 0; k < 1024; k++) v |= ei32[2 * k + 1];
    g_i64 = (v == 0) ? 1 : 0;
}

__device__ __forceinline__ int load_edge(const void* ei, int idx) {
    if (g_i64) return (int)((const long long*)ei)[idx];
    return ((const int*)ei)[idx];
}

// ---------------------------------------------------------------------------
__global__ void init_kernel() {
    int i = blockIdx.x * blockDim.x + threadIdx.x;
    if (i < N_NODES) g_cnt[i] = 0;
    if (i < 2 * HC)  g_stat[i] = 0.f;
}

// ---------------------------------------------------------------------------
// GEMM: g_h = x @ W   (100000x128 @ 128x256), 64x256 block tile, 8x8 thread tile
__global__ __launch_bounds__(256) void gemm_kernel(const float* __restrict__ x,
                                                   const float* __restrict__ W) {
    __shared__ float Ws[16][256];
    __shared__ float Xs[16][64];
    const int rowbase = blockIdx.x * 64;
    const int tid = threadIdx.x;
    const int ty = tid >> 5;      // warp id 0..7  -> row group
    const int tx = tid & 31;      // lane          -> col group
    float acc[8][8] = {};

    for (int k0 = 0; k0 < IN_C; k0 += 16) {
        // stage W tile: 16x256 floats = 1024 float4, 4 per thread
        #pragma unroll
        for (int i = 0; i < 4; i++) {
            int idx = tid + i * 256;          // float4 index
            int k = idx >> 6, c4 = idx & 63;
            float4 w = *(const float4*)(W + (k0 + k) * 256 + c4 * 4);
            *(float4*)(&Ws[k][c4 * 4]) = w;
        }
        // stage X tile transposed: Xs[k][row]
        {
            int r = tid >> 2, kq = tid & 3;
            int row = rowbase + r;
            float4 xv = make_float4(0.f, 0.f, 0.f, 0.f);
            if (row < N_NODES)
                xv = *(const float4*)(x + row * IN_C + k0 + kq * 4);
            Xs[kq * 4 + 0][r] = xv.x; Xs[kq * 4 + 1][r] = xv.y;
            Xs[kq * 4 + 2][r] = xv.z; Xs[kq * 4 + 3][r] = xv.w;
        }
        __syncthreads();
        #pragma unroll
        for (int k = 0; k < 16; k++) {
            float xf[8], wf[8];
            *(float4*)(xf)     = *(float4*)&Xs[k][ty * 8];
            *(float4*)(xf + 4) = *(float4*)&Xs[k][ty * 8 + 4];
            *(float4*)(wf)     = *(float4*)&Ws[k][tx * 8];
            *(float4*)(wf + 4) = *(float4*)&Ws[k][tx * 8 + 4];
            #pragma unroll
            for (int i = 0; i < 8; i++)
                #pragma unroll
                for (int j = 0; j < 8; j++)
                    acc[i][j] += xf[i] * wf[j];
        }
        __syncthreads();
    }
    #pragma unroll
    for (int i = 0; i < 8; i++) {
        int row = rowbase + ty * 8 + i;
        if (row < N_NODES) {
            *(float4*)(g_h + row * 256 + tx * 8) =
                make_float4(acc[i][0], acc[i][1], acc[i][2], acc[i][3]);
            *(float4*)(g_h + row * 256 + tx * 8 + 4) =
                make_float4(acc[i][4], acc[i][5], acc[i][6], acc[i][7]);
        }
    }
}

// ---------------------------------------------------------------------------
// per-(node,head) attention coefficients: warp-per-task 64-dot
__global__ __launch_bounds__(256) void acoef_kernel(const float* __restrict__ att_src,
                                                    const float* __restrict__ att_dst) {
    int w = blockIdx.x * 8 + (threadIdx.x >> 5);
    int lane = threadIdx.x & 31;
    if (w >= N_NODES * NHEAD) return;
    int node = w >> 2, head = w & 3;
    const float* hp = g_h + node * 256 + head * 64;
    float v1 = hp[lane], v2 = hp[lane + 32];
    float as = v1 * att_src[head * 64 + lane] + v2 * att_src[head * 64 + lane + 32];
    float ad = v1 * att_dst[head * 64 + lane] + v2 * att_dst[head * 64 + lane + 32];
    #pragma unroll
    for (int o = 16; o; o >>= 1) {
        as += __shfl_xor_sync(0xFFFFFFFFu, as, o);
        ad += __shfl_xor_sync(0xFFFFFFFFu, ad, o);
    }
    if (lane == 0) { g_asrc[node * 4 + head] = as; g_adst[node * 4 + head] = ad; }
}

// ---------------------------------------------------------------------------
__global__ void hist_kernel(const void* __restrict__ ei) {
    int i = blockIdx.x * blockDim.x + threadIdx.x;
    if (i < NE) {
        int d = load_edge(ei, NE + i);
        if ((unsigned)d < (unsigned)N_NODES) atomicAdd(&g_cnt[d], 1);
    }
}

__global__ __launch_bounds__(1024) void scan1_kernel() {
    __shared__ int sh[1024];
    int i = blockIdx.x * 1024 + threadIdx.x;
    int v = (i < N_NODES) ? g_cnt[i] : 0;
    sh[threadIdx.x] = v; __syncthreads();
    for (int off = 1; off < 1024; off <<= 1) {
        int t = (threadIdx.x >= off) ? sh[threadIdx.x - off] : 0;
        __syncthreads();
        sh[threadIdx.x] += t; __syncthreads();
    }
    if (i < N_NODES) g_rowptr[i] = sh[threadIdx.x] - v;  // exclusive
    if (threadIdx.x == 1023) g_part[blockIdx.x] = sh[1023];
}

__global__ __launch_bounds__(128) void scan2_kernel(int nb) {
    __shared__ int sh[128];
    int v = (threadIdx.x < nb) ? g_part[threadIdx.x] : 0;
    sh[threadIdx.x] = v; __syncthreads();
    for (int off = 1; off < 128; off <<= 1) {
        int t = (threadIdx.x >= off) ? sh[threadIdx.x - off] : 0;
        __syncthreads();
        sh[threadIdx.x] += t; __syncthreads();
    }
    if (threadIdx.x < nb) g_part2[threadIdx.x] = sh[threadIdx.x] - v;
    if (threadIdx.x == nb - 1) g_rowptr[N_NODES] = sh[threadIdx.x]; // total valid
}

__global__ __launch_bounds__(1024) void scan3_kernel() {
    int i = blockIdx.x * 1024 + threadIdx.x;
    if (i < N_NODES) {
        int v = g_rowptr[i] + g_part2[blockIdx.x];
        g_rowptr[i] = v;
        g_fill[i] = v;
    }
}

__global__ void fill_kernel(const void* __restrict__ ei) {
    int i = blockIdx.x * blockDim.x + threadIdx.x;
    if (i < NE) {
        int s = load_edge(ei, i);
        int d = load_edge(ei, NE + i);
        if ((unsigned)s < (unsigned)N_NODES && (unsigned)d < (unsigned)N_NODES) {
            int pos = atomicAdd(&g_fill[d], 1);
            g_csr[pos] = s;
        }
    }
}

// ---------------------------------------------------------------------------
// per-destination-node softmax + weighted aggregate. One block per node,
// thread t owns channel t -> every h[src] gather is a coalesced 1KB row read.
__global__ __launch_bounds__(256) void agg_kernel(const float* __restrict__ bias,
                                                  float* __restrict__ out) {
    const int i = blockIdx.x;
    const int tid = threadIdx.x;
    __shared__ float sadst[4], sden[4], sinv[4], sself[4];
    __shared__ int   ssrc[64];
    __shared__ float sal[64][4];

    const int ebase = g_rowptr[i];
    const int deg = g_rowptr[i + 1] - ebase;

    if (tid < 4) { sadst[tid] = g_adst[i * 4 + tid]; sden[tid] = 0.f; }
    __syncthreads();
    if (tid < 4) {  // self-loop logit
        float e = g_asrc[i * 4 + tid] + sadst[tid];
        e = e > 0.f ? e : NEG * e;
        float ex = __expf(e);
        sself[tid] = ex;
        atomicAdd(&sden[tid], ex);
    }
    for (int j = tid; j < deg * 4; j += 256) {
        int s = g_csr[ebase + (j >> 2)];
        int hd = j & 3;
        float e = g_asrc[s * 4 + hd] + sadst[hd];
        e = e > 0.f ? e : NEG * e;
        atomicAdd(&sden[hd], __expf(e));
    }
    __syncthreads();
    if (tid < 4) sinv[tid] = 1.f / (sden[tid] + 1e-16f);
    __syncthreads();

    const int hd = tid >> 6;
    const float inv = sinv[hd];
    float a0, a1 = 0.f, a2 = 0.f, a3 = 0.f;
    a0 = g_h[i * 256 + tid] * (sself[hd] * inv);   // self-loop contribution

    for (int base = 0; base < deg; base += 64) {
        int m = min(64, deg - base);
        if (tid < m) ssrc[tid] = g_csr[ebase + base + tid];
        for (int j = tid; j < m * 4; j += 256) {
            int s = g_csr[ebase + base + (j >> 2)];
            int h2 = j & 3;
            float e = g_asrc[s * 4 + h2] + sadst[h2];
            e = e > 0.f ? e : NEG * e;
            sal[j >> 2][h2] = __expf(e) * sinv[h2];
        }
        __syncthreads();
        int j = 0;
        for (; j + 4 <= m; j += 4) {   // 4-way MLP for latency hiding
            int s0 = ssrc[j], s1 = ssrc[j + 1], s2 = ssrc[j + 2], s3 = ssrc[j + 3];
            a0 += g_h[s0 * 256 + tid] * sal[j][hd];
            a1 += g_h[s1 * 256 + tid] * sal[j + 1][hd];
            a2 += g_h[s2 * 256 + tid] * sal[j + 2][hd];
            a3 += g_h[s3 * 256 + tid] * sal[j + 3][hd];
        }
        for (; j < m; j++)
            a0 += g_h[ssrc[j] * 256 + tid] * sal[j][hd];
        __syncthreads();
    }
    out[i * 256 + tid] = a0 + a1 + a2 + a3 + bias[tid];
}

// ---------------------------------------------------------------------------
__global__ __launch_bounds__(256) void bnstat_kernel(const float* __restrict__ out) {
    int t = threadIdx.x;
    int r0 = blockIdx.x * 256;
    int rmax = min(256, N_NODES - r0);
    float s = 0.f, s2 = 0.f;
    for (int r = 0; r < rmax; r++) {
        float v = out[(size_t)(r0 + r) * 256 + t];
        s += v; s2 += v * v;
    }
    atomicAdd(&g_stat[t], s);
    atomicAdd(&g_stat[256 + t], s2);
}

__global__ __launch_bounds__(256) void bnfin_kernel(const float* __restrict__ gamma,
                                                    const float* __restrict__ beta) {
    int t = threadIdx.x;
    float invN = 1.f / (float)N_NODES;
    float mean = g_stat[t] * invN;
    float var = g_stat[256 + t] * invN - mean * mean;
    float sc = gamma[t] * rsqrtf(var + BNEPS);
    g_scale[t] = sc;
    g_shift[t] = beta[t] - mean * sc;
}

__global__ __launch_bounds__(256) void final_kernel(float* __restrict__ out) {
    int i4 = blockIdx.x * 256 + threadIdx.x;             // float4 index
    if (i4 >= N_NODES * (HC / 4)) return;
    int c = (i4 & 63) * 4;
    float4 v = ((float4*)out)[i4];
    float f;
    f = g_scale[c + 0] * v.x + g_shift[c + 0]; v.x = f > 0.f ? f : expm1f(f);
    f = g_scale[c + 1] * v.y + g_shift[c + 1]; v.y = f > 0.f ? f : expm1f(f);
    f = g_scale[c + 2] * v.z + g_shift[c + 2]; v.z = f > 0.f ? f : expm1f(f);
    f = g_scale[c + 3] * v.w + g_shift[c + 3]; v.w = f > 0.f ? f : expm1f(f);
    ((float4*)out)[i4] = v;
}

// ---------------------------------------------------------------------------
extern "C" void kernel_launch(void* const* d_in, const int* in_sizes, int n_in,
                              void* d_out, int out_size) {
    const float* x       = (const float*)d_in[0];
    const void*  ei      = d_in[1];
    const float* W       = (const float*)d_in[2];
    const float* att_src = (const float*)d_in[3];
    const float* att_dst = (const float*)d_in[4];
    const float* bias    = (const float*)d_in[5];
    const float* gamma   = (const float*)d_in[6];
    const float* beta    = (const float*)d_in[7];
    float* out = (float*)d_out;

    probe_kernel<<<1, 1>>>((const int*)ei);
    init_kernel<<<(N_NODES + 255) / 256, 256>>>();

    gemm_kernel<<<(N_NODES + 63) / 64, 256>>>(x, W);
    acoef_kernel<<<(N_NODES * NHEAD + 7) / 8, 256>>>(att_src, att_dst);

    hist_kernel<<<(NE + 255) / 256, 256>>>(ei);
    int nb = (N_NODES + 1023) / 1024;   // 98
    scan1_kernel<<<nb, 1024>>>();
    scan2_kernel<<<1, 128>>>(nb);
    scan3_kernel<<<nb, 1024>>>();
    fill_kernel<<<(NE + 255) / 256, 256>>>(ei);

    agg_kernel<<<N_NODES, 256>>>(bias, out);

    bnstat_kernel<<<(N_NODES + 255) / 256, 256>>>(out);
    bnfin_kernel<<<1, 256>>>(gamma, beta);
    final_kernel<<<(N_NODES * (HC / 4) + 255) / 256, 256>>>(out);
}